// round 5
// baseline (speedup 1.0000x reference)
#include <cuda_runtime.h>
#include <math.h>
#include <stdint.h>

#define S_LEN 2048
#define B_SZ  2
#define NH    32
#define NKV   8
#define HD    128
#define HID   4096
#define QSZ   (NH*HD)        // 4096
#define KVSZ  (NKV*HD)       // 1024
#define QKVW  (QSZ + 2*KVSZ) // 6144
#define NTOK  (B_SZ*S_LEN)   // 4096

// Scratch (device globals: allocation-free per harness rules)
__device__ float g_qkv [(size_t)NTOK * QKVW];   // 100 MB
__device__ float g_attn[(size_t)NTOK * QSZ];    // 67 MB
__device__ float g_hid [(size_t)NTOK * HID];    // 67 MB  (tf32-rounded hidden)
__device__ float g_wqkv[(size_t)HID * QKVW];    // 100 MB (tf32-rounded w_qkv)
__device__ float g_wo  [(size_t)QSZ * HID];     // 67 MB  (tf32-rounded w_o)

// ---------------------------------------------------------------------------
// tf32 helpers
// ---------------------------------------------------------------------------
__device__ __forceinline__ uint32_t f2tf32(float x) {
    uint32_t r;
    asm("cvt.rna.tf32.f32 %0, %1;" : "=r"(r) : "f"(x));
    return r;
}
__device__ __forceinline__ float rnd_tf32(float x) {
    return __uint_as_float(f2tf32(x));
}

__device__ __forceinline__ void mma_tf32(float4& c, const uint32_t a[4], const uint32_t b[2]) {
    asm volatile(
        "mma.sync.aligned.m16n8k8.row.col.f32.tf32.tf32.f32 "
        "{%0,%1,%2,%3}, {%4,%5,%6,%7}, {%8,%9}, {%0,%1,%2,%3};\n"
        : "+f"(c.x), "+f"(c.y), "+f"(c.z), "+f"(c.w)
        : "r"(a[0]), "r"(a[1]), "r"(a[2]), "r"(a[3]),
          "r"(b[0]), "r"(b[1]));
}

__device__ __forceinline__ void cp_async16(void* smem, const void* gmem) {
    uint32_t s = (uint32_t)__cvta_generic_to_shared(smem);
    asm volatile("cp.async.cg.shared.global [%0], [%1], 16;\n" :: "r"(s), "l"(gmem));
}
#define CP_COMMIT() asm volatile("cp.async.commit_group;\n" ::: "memory")
#define CP_WAIT0()  asm volatile("cp.async.wait_group 0;\n" ::: "memory")

// ---------------------------------------------------------------------------
// Elementwise tf32 pre-rounding: out[i] = tf32(in[i]) (rna). n % 4 == 0.
// ---------------------------------------------------------------------------
__global__ __launch_bounds__(256) void round_tf32_kernel(const float4* __restrict__ in,
                                                         float4* __restrict__ out, int n4) {
    int i = blockIdx.x * blockDim.x + threadIdx.x;
    if (i < n4) {
        float4 v = in[i];
        v.x = rnd_tf32(v.x); v.y = rnd_tf32(v.y);
        v.z = rnd_tf32(v.z); v.w = rnd_tf32(v.w);
        out[i] = v;
    }
}

// ---------------------------------------------------------------------------
// TF32 tensor-core GEMM: C[M,N] = A[M,K]*B[K,N], row-major. Operands MUST be
// pre-rounded to tf32 (no cvt in the inner loop). 128x128 tile, BK=16,
// 8 warps (64x32 warp tile), cp.async double-buffered.
// RND: round C to tf32 on store (for tensors feeding later mma stages).
// ---------------------------------------------------------------------------
#define APAD 20
#define BPAD 132

template<bool RND>
__global__ __launch_bounds__(256, 2) void gemm_tf32(const float* __restrict__ A,
                                                    const float* __restrict__ B,
                                                    float* __restrict__ C,
                                                    int M, int N, int K) {
    __shared__ float As[2][128 * APAD];
    __shared__ float Bs[2][16 * BPAD];

    const int tid   = threadIdx.x;
    const int wid   = tid >> 5;
    const int lane  = tid & 31;
    const int group = lane >> 2;
    const int tig   = lane & 3;

    const int m0 = blockIdx.y * 128;
    const int n0 = blockIdx.x * 128;
    const int wm = (wid & 1) * 64;
    const int wn = (wid >> 1) * 32;

    float4 acc[4][4];
#pragma unroll
    for (int mt = 0; mt < 4; mt++)
#pragma unroll
        for (int nt = 0; nt < 4; nt++) acc[mt][nt] = make_float4(0.f, 0.f, 0.f, 0.f);

    auto load_tiles = [&](int buf, int k0) {
#pragma unroll
        for (int u = 0; u < 2; u++) {
            int id = tid + u * 256;
            int r  = id >> 2;
            int kc = (id & 3) * 4;
            cp_async16(&As[buf][r * APAD + kc],
                       &A[(size_t)(m0 + r) * K + k0 + kc]);
        }
#pragma unroll
        for (int u = 0; u < 2; u++) {
            int id = tid + u * 256;
            int kr = id >> 5;
            int nc = (id & 31) * 4;
            cp_async16(&Bs[buf][kr * BPAD + nc],
                       &B[(size_t)(k0 + kr) * N + n0 + nc]);
        }
    };

    load_tiles(0, 0);
    CP_COMMIT();

    const int nIter = K / 16;
    for (int it = 0; it < nIter; ++it) {
        CP_WAIT0();
        __syncthreads();
        if (it + 1 < nIter) {
            load_tiles((it + 1) & 1, (it + 1) * 16);
            CP_COMMIT();
        }
        const int buf = it & 1;
        const float* __restrict__ as = As[buf];
        const float* __restrict__ bs = Bs[buf];

#pragma unroll
        for (int ks = 0; ks < 2; ks++) {
            uint32_t af[4][4];
            uint32_t bf[4][2];
            const int cb = ks * 8 + tig;
#pragma unroll
            for (int mt = 0; mt < 4; mt++) {
                int r = wm + mt * 16 + group;
                af[mt][0] = __float_as_uint(as[r * APAD + cb]);
                af[mt][1] = __float_as_uint(as[(r + 8) * APAD + cb]);
                af[mt][2] = __float_as_uint(as[r * APAD + cb + 4]);
                af[mt][3] = __float_as_uint(as[(r + 8) * APAD + cb + 4]);
            }
            const int kr = ks * 8 + tig;
#pragma unroll
            for (int nt = 0; nt < 4; nt++) {
                int col = wn + nt * 8 + group;
                bf[nt][0] = __float_as_uint(bs[kr * BPAD + col]);
                bf[nt][1] = __float_as_uint(bs[(kr + 4) * BPAD + col]);
            }
#pragma unroll
            for (int mt = 0; mt < 4; mt++)
#pragma unroll
                for (int nt = 0; nt < 4; nt++) mma_tf32(acc[mt][nt], af[mt], bf[nt]);
        }
        __syncthreads();
    }

#pragma unroll
    for (int mt = 0; mt < 4; mt++) {
        int r = m0 + wm + mt * 16 + group;
#pragma unroll
        for (int nt = 0; nt < 4; nt++) {
            int cc = n0 + wn + nt * 8 + tig * 2;
            float4 v = acc[mt][nt];
            if (RND) {
                v.x = rnd_tf32(v.x); v.y = rnd_tf32(v.y);
                v.z = rnd_tf32(v.z); v.w = rnd_tf32(v.w);
            }
            *(float2*)&C[(size_t)r * N + cc]       = make_float2(v.x, v.y);
            *(float2*)&C[(size_t)(r + 8) * N + cc] = make_float2(v.z, v.w);
        }
    }
}

// ---------------------------------------------------------------------------
// RoPE in-place on q (heads 0..31) and k (heads 32..39); outputs tf32-rounded.
// ---------------------------------------------------------------------------
__global__ __launch_bounds__(256) void rope_kernel(float* __restrict__ qkv,
                                                   const int* __restrict__ positions) {
    const int token = blockIdx.x;
    const float pos = (float)positions[token];
    float* base_tok = qkv + (size_t)token * QKVW;
#pragma unroll
    for (int it = 0; it < 10; ++it) {
        int idx = it * 256 + threadIdx.x;
        int head = idx >> 6;
        int i = idx & 63;
        float inv_freq = 1.0f / powf(10000.0f, (float)i * (1.0f / 64.0f));
        float ang = pos * inv_freq;
        float cs = cosf(ang);
        float sn = sinf(ang);
        float* p = base_tok + head * HD;
        float x1 = p[i];
        float x2 = p[i + 64];
        p[i]      = rnd_tf32(x1 * cs - x2 * sn);
        p[i + 64] = rnd_tf32(x2 * cs + x1 * sn);
    }
}

// ---------------------------------------------------------------------------
// Tensor-core flash attention (tf32 mma, fp32 accum), causal.
// Block = 256 thr = 8 warps. Tile: 128 queries x 64 KV. Each warp owns 16
// query rows. Q/K/V/P staged in dynamic smem with conflict-free strides.
// Fragment maps (m16n8k8): A: a0=(g,t) a1=(g+8,t) a2=(g,t+4) a3=(g+8,t+4);
// B(col): b0=(k=t,n=g) b1=(k=t+4,n=g); C: (g,2t),(g,2t+1),(g+8,2t),(g+8,2t+1).
// ---------------------------------------------------------------------------
#define AT_BM 128
#define AT_BN 64
#define QS_STR 132
#define KS_STR 132
#define VS_STR 136
#define PS_STR 68
#define KS_OFF (AT_BM * QS_STR)            // 16896
#define VS_OFF (KS_OFF + AT_BN * KS_STR)   // 25344
#define PS_OFF (VS_OFF + AT_BN * VS_STR)   // 34048
#define AT_SMEM_FLOATS (PS_OFF + AT_BM * PS_STR)   // 42752
#define AT_SMEM_BYTES  (AT_SMEM_FLOATS * 4)        // 171008

__global__ __launch_bounds__(256, 1) void attn_tc(const float* __restrict__ qkv,
                                                  float* __restrict__ outp) {
    extern __shared__ float smf[];
    float* Qs = smf;
    float* Ks = smf + KS_OFF;
    float* Vs = smf + VS_OFF;
    float* Ps = smf + PS_OFF;

    const int tid  = threadIdx.x;
    const int warp = tid >> 5, lane = tid & 31;
    const int g    = lane >> 2, tig = lane & 3;
    const int qt   = gridDim.x - 1 - blockIdx.x;   // big tiles first
    const int h    = blockIdx.y, b = blockIdx.z;
    const int q0   = qt * AT_BM;
    const int wm   = warp * 16;

    // Load Q tile (pre-rounded by rope): 128 x 128
    const float* qbase = qkv + ((size_t)(b * S_LEN + q0)) * QKVW + h * HD;
#pragma unroll
    for (int u = 0; u < 16; u++) {
        int idx = tid + u * 256;
        int row = idx >> 5, c4 = idx & 31;
        *(float4*)&Qs[row * QS_STR + c4 * 4] =
            *(const float4*)(qbase + (size_t)row * QKVW + c4 * 4);
    }

    float4 o[16];
#pragma unroll
    for (int i = 0; i < 16; i++) o[i] = make_float4(0.f, 0.f, 0.f, 0.f);
    float m_lo = -INFINITY, m_hi = -INFINITY, l_lo = 0.f, l_hi = 0.f;

    const int kvh = h >> 2;                       // NH/NKV = 4
    const float* kbase = qkv + (size_t)b * S_LEN * QKVW + QSZ + kvh * HD;
    const int ntiles = (q0 + AT_BM) / AT_BN;
    const int row_lo = q0 + wm + g;
    const int warp_last_ks = q0 + wm + 15;        // last useful kv index for warp
    const float scale = 0.08838834764831845f;     // 1/sqrt(128)

    for (int tile = 0; tile < ntiles; tile++) {
        const int ks0 = tile * AT_BN;
        __syncthreads();   // previous iter's K/V reads done before overwrite
#pragma unroll
        for (int u = 0; u < 8; u++) {
            int idx = tid + u * 256;
            int row = idx >> 5, c4 = idx & 31;
            const float* src = kbase + (size_t)(ks0 + row) * QKVW + c4 * 4;
            cp_async16(&Ks[row * KS_STR + c4 * 4], src);
            cp_async16(&Vs[row * VS_STR + c4 * 4], src + KVSZ);
        }
        CP_COMMIT();
        CP_WAIT0();
        __syncthreads();

        if (ks0 > warp_last_ks) continue;  // tile fully masked for this warp

        // ---- S = scale * Q K^T  (16 k-steps over HD) ----
        float4 s[8];
#pragma unroll
        for (int nt = 0; nt < 8; nt++) s[nt] = make_float4(0.f, 0.f, 0.f, 0.f);
#pragma unroll
        for (int k = 0; k < 16; k++) {
            const int kc = k * 8 + tig;
            uint32_t a[4];
            a[0] = __float_as_uint(Qs[(wm + g) * QS_STR + kc]);
            a[1] = __float_as_uint(Qs[(wm + g + 8) * QS_STR + kc]);
            a[2] = __float_as_uint(Qs[(wm + g) * QS_STR + kc + 4]);
            a[3] = __float_as_uint(Qs[(wm + g + 8) * QS_STR + kc + 4]);
#pragma unroll
            for (int nt = 0; nt < 8; nt++) {
                uint32_t bb[2];
                bb[0] = __float_as_uint(Ks[(nt * 8 + g) * KS_STR + kc]);
                bb[1] = __float_as_uint(Ks[(nt * 8 + g) * KS_STR + kc + 4]);
                mma_tf32(s[nt], a, bb);
            }
        }

        // ---- scale + causal mask + row max ----
        float tmax_lo = -1e30f, tmax_hi = -1e30f;
#pragma unroll
        for (int nt = 0; nt < 8; nt++) {
            int col = ks0 + nt * 8 + 2 * tig;
            float4& v = s[nt];
            v.x *= scale; v.y *= scale; v.z *= scale; v.w *= scale;
            if (col     > row_lo)     v.x = -1e30f;
            if (col + 1 > row_lo)     v.y = -1e30f;
            if (col     > row_lo + 8) v.z = -1e30f;
            if (col + 1 > row_lo + 8) v.w = -1e30f;
            tmax_lo = fmaxf(tmax_lo, fmaxf(v.x, v.y));
            tmax_hi = fmaxf(tmax_hi, fmaxf(v.z, v.w));
        }
        tmax_lo = fmaxf(tmax_lo, __shfl_xor_sync(0xffffffffu, tmax_lo, 1));
        tmax_lo = fmaxf(tmax_lo, __shfl_xor_sync(0xffffffffu, tmax_lo, 2));
        tmax_hi = fmaxf(tmax_hi, __shfl_xor_sync(0xffffffffu, tmax_hi, 1));
        tmax_hi = fmaxf(tmax_hi, __shfl_xor_sync(0xffffffffu, tmax_hi, 2));

        float mn_lo = fmaxf(m_lo, tmax_lo);
        float mn_hi = fmaxf(m_hi, tmax_hi);
        float corr_lo = __expf(m_lo - mn_lo);
        float corr_hi = __expf(m_hi - mn_hi);
        m_lo = mn_lo; m_hi = mn_hi;

        // ---- exp + P store (tf32 rounded) + partial row sums ----
        float ps_lo = 0.f, ps_hi = 0.f;
#pragma unroll
        for (int nt = 0; nt < 8; nt++) {
            float4 v = s[nt];
            float ex = __expf(v.x - m_lo), ey = __expf(v.y - m_lo);
            float ez = __expf(v.z - m_hi), ew = __expf(v.w - m_hi);
            ps_lo += ex + ey;
            ps_hi += ez + ew;
            *(float2*)&Ps[(wm + g) * PS_STR + nt * 8 + 2 * tig] =
                make_float2(rnd_tf32(ex), rnd_tf32(ey));
            *(float2*)&Ps[(wm + g + 8) * PS_STR + nt * 8 + 2 * tig] =
                make_float2(rnd_tf32(ez), rnd_tf32(ew));
        }
        l_lo = l_lo * corr_lo + ps_lo;
        l_hi = l_hi * corr_hi + ps_hi;
#pragma unroll
        for (int i = 0; i < 16; i++) {
            o[i].x *= corr_lo; o[i].y *= corr_lo;
            o[i].z *= corr_hi; o[i].w *= corr_hi;
        }
        __syncwarp();   // Ps rows wm..wm+15 written & read by this warp only

        // ---- O += P V  (8 k-steps over BN, 16 n-tiles over HD) ----
#pragma unroll
        for (int k = 0; k < 8; k++) {
            const int kc = k * 8 + tig;
            uint32_t a[4];
            a[0] = __float_as_uint(Ps[(wm + g) * PS_STR + kc]);
            a[1] = __float_as_uint(Ps[(wm + g + 8) * PS_STR + kc]);
            a[2] = __float_as_uint(Ps[(wm + g) * PS_STR + kc + 4]);
            a[3] = __float_as_uint(Ps[(wm + g + 8) * PS_STR + kc + 4]);
#pragma unroll
            for (int ot = 0; ot < 16; ot++) {
                uint32_t bb[2];
                bb[0] = __float_as_uint(Vs[kc * VS_STR + ot * 8 + g]);
                bb[1] = __float_as_uint(Vs[(kc + 4) * VS_STR + ot * 8 + g]);
                mma_tf32(o[ot], a, bb);
            }
        }
    }

    // ---- epilogue: finish row sums, normalize, write tf32-rounded ----
    l_lo += __shfl_xor_sync(0xffffffffu, l_lo, 1);
    l_lo += __shfl_xor_sync(0xffffffffu, l_lo, 2);
    l_hi += __shfl_xor_sync(0xffffffffu, l_hi, 1);
    l_hi += __shfl_xor_sync(0xffffffffu, l_hi, 2);
    const float inv_lo = 1.f / l_lo;
    const float inv_hi = 1.f / l_hi;

    float* op_lo = outp + ((size_t)(b * S_LEN + row_lo)) * QSZ + h * HD;
    float* op_hi = op_lo + (size_t)8 * QSZ;
#pragma unroll
    for (int ot = 0; ot < 16; ot++) {
        int cc = ot * 8 + 2 * tig;
        *(float2*)&op_lo[cc] = make_float2(rnd_tf32(o[ot].x * inv_lo),
                                           rnd_tf32(o[ot].y * inv_lo));
        *(float2*)&op_hi[cc] = make_float2(rnd_tf32(o[ot].z * inv_hi),
                                           rnd_tf32(o[ot].w * inv_hi));
    }
}

// ---------------------------------------------------------------------------
// Launch: pre-round -> QKV GEMM (tf32) -> RoPE -> TC flash attn -> out GEMM
// ---------------------------------------------------------------------------
extern "C" void kernel_launch(void* const* d_in, const int* in_sizes, int n_in,
                              void* d_out, int out_size) {
    const int*   positions = (const int*)d_in[0];
    const float* hidden    = (const float*)d_in[1];
    const float* w_qkv     = (const float*)d_in[2];
    const float* w_o       = (const float*)d_in[3];
    float* out = (float*)d_out;

    float *qkv, *attn, *hid_r, *wqkv_r, *wo_r;
    cudaGetSymbolAddress((void**)&qkv,    g_qkv);
    cudaGetSymbolAddress((void**)&attn,   g_attn);
    cudaGetSymbolAddress((void**)&hid_r,  g_hid);
    cudaGetSymbolAddress((void**)&wqkv_r, g_wqkv);
    cudaGetSymbolAddress((void**)&wo_r,   g_wo);

    cudaFuncSetAttribute(attn_tc, cudaFuncAttributeMaxDynamicSharedMemorySize,
                         AT_SMEM_BYTES);

    // 0) Pre-round operands to tf32 (hoists all cvt out of GEMM inner loops)
    {
        int n4 = (NTOK * HID) / 4;
        round_tf32_kernel<<<(n4 + 255) / 256, 256>>>((const float4*)hidden, (float4*)hid_r, n4);
        n4 = (HID * QKVW) / 4;
        round_tf32_kernel<<<(n4 + 255) / 256, 256>>>((const float4*)w_qkv, (float4*)wqkv_r, n4);
        n4 = (QSZ * HID) / 4;
        round_tf32_kernel<<<(n4 + 255) / 256, 256>>>((const float4*)w_o, (float4*)wo_r, n4);
    }
    // 1) QKV projection (rounded epilogue: V feeds attention mma directly)
    gemm_tf32<true><<<dim3(QKVW / 128, NTOK / 128), 256>>>(hid_r, wqkv_r, qkv, NTOK, QKVW, HID);
    // 2) RoPE on q,k (tf32-rounded outputs)
    rope_kernel<<<NTOK, 256>>>(qkv, positions);
    // 3) Tensor-core causal flash attention
    attn_tc<<<dim3(S_LEN / AT_BM, NH, B_SZ), 256, AT_SMEM_BYTES>>>(qkv, attn);
    // 4) Output projection (full fp32 store)
    gemm_tf32<false><<<dim3(HID / 128, NTOK / 128), 256>>>(attn, wo_r, out, NTOK, HID, QSZ);
}

// round 6
// speedup vs baseline: 1.0012x; 1.0012x over previous
#include <cuda_runtime.h>
#include <math.h>
#include <stdint.h>

#define S_LEN 2048
#define B_SZ  2
#define NH    32
#define NKV   8
#define HD    128
#define HID   4096
#define QSZ   (NH*HD)        // 4096
#define KVSZ  (NKV*HD)       // 1024
#define QKVW  (QSZ + 2*KVSZ) // 6144
#define NTOK  (B_SZ*S_LEN)   // 4096

// Scratch (device globals: allocation-free per harness rules)
__device__ float g_qkv [(size_t)NTOK * QKVW];   // 100 MB
__device__ float g_attn[(size_t)NTOK * QSZ];    // 67 MB
__device__ float g_hid [(size_t)NTOK * HID];    // 67 MB  (tf32-rounded hidden)
__device__ float g_wqkv[(size_t)HID * QKVW];    // 100 MB (tf32-rounded w_qkv)
__device__ float g_wo  [(size_t)QSZ * HID];     // 67 MB  (tf32-rounded w_o)

// ---------------------------------------------------------------------------
// tf32 helpers
// ---------------------------------------------------------------------------
__device__ __forceinline__ uint32_t f2tf32(float x) {
    uint32_t r;
    asm("cvt.rna.tf32.f32 %0, %1;" : "=r"(r) : "f"(x));
    return r;
}
__device__ __forceinline__ float rnd_tf32(float x) {
    return __uint_as_float(f2tf32(x));
}

__device__ __forceinline__ void mma_tf32(float4& c, const uint32_t a[4], const uint32_t b[2]) {
    asm volatile(
        "mma.sync.aligned.m16n8k8.row.col.f32.tf32.tf32.f32 "
        "{%0,%1,%2,%3}, {%4,%5,%6,%7}, {%8,%9}, {%0,%1,%2,%3};\n"
        : "+f"(c.x), "+f"(c.y), "+f"(c.z), "+f"(c.w)
        : "r"(a[0]), "r"(a[1]), "r"(a[2]), "r"(a[3]),
          "r"(b[0]), "r"(b[1]));
}

__device__ __forceinline__ void cp_async16(void* smem, const void* gmem) {
    uint32_t s = (uint32_t)__cvta_generic_to_shared(smem);
    asm volatile("cp.async.cg.shared.global [%0], [%1], 16;\n" :: "r"(s), "l"(gmem));
}
#define CP_COMMIT() asm volatile("cp.async.commit_group;\n" ::: "memory")
#define CP_WAIT0()  asm volatile("cp.async.wait_group 0;\n" ::: "memory")

// ---------------------------------------------------------------------------
// Elementwise tf32 pre-rounding: out[i] = tf32(in[i]) (rna). n % 4 == 0.
// ---------------------------------------------------------------------------
__global__ __launch_bounds__(256) void round_tf32_kernel(const float4* __restrict__ in,
                                                         float4* __restrict__ out, int n4) {
    int i = blockIdx.x * blockDim.x + threadIdx.x;
    if (i < n4) {
        float4 v = in[i];
        v.x = rnd_tf32(v.x); v.y = rnd_tf32(v.y);
        v.z = rnd_tf32(v.z); v.w = rnd_tf32(v.w);
        out[i] = v;
    }
}

// ---------------------------------------------------------------------------
// TF32 tensor-core GEMM: C[M,N] = A[M,K]*B[K,N], row-major. Operands MUST be
// pre-rounded to tf32 (no cvt in the inner loop). 128x128 tile, BK=16,
// 8 warps (64x32 warp tile), cp.async double-buffered.
// RND: round C to tf32 on store (for tensors feeding later mma stages).
// ---------------------------------------------------------------------------
#define APAD 20
#define BPAD 132

template<bool RND>
__global__ __launch_bounds__(256, 2) void gemm_tf32(const float* __restrict__ A,
                                                    const float* __restrict__ B,
                                                    float* __restrict__ C,
                                                    int M, int N, int K) {
    __shared__ float As[2][128 * APAD];
    __shared__ float Bs[2][16 * BPAD];

    const int tid   = threadIdx.x;
    const int wid   = tid >> 5;
    const int lane  = tid & 31;
    const int group = lane >> 2;
    const int tig   = lane & 3;

    const int m0 = blockIdx.y * 128;
    const int n0 = blockIdx.x * 128;
    const int wm = (wid & 1) * 64;
    const int wn = (wid >> 1) * 32;

    float4 acc[4][4];
#pragma unroll
    for (int mt = 0; mt < 4; mt++)
#pragma unroll
        for (int nt = 0; nt < 4; nt++) acc[mt][nt] = make_float4(0.f, 0.f, 0.f, 0.f);

    auto load_tiles = [&](int buf, int k0) {
#pragma unroll
        for (int u = 0; u < 2; u++) {
            int id = tid + u * 256;
            int r  = id >> 2;
            int kc = (id & 3) * 4;
            cp_async16(&As[buf][r * APAD + kc],
                       &A[(size_t)(m0 + r) * K + k0 + kc]);
        }
#pragma unroll
        for (int u = 0; u < 2; u++) {
            int id = tid + u * 256;
            int kr = id >> 5;
            int nc = (id & 31) * 4;
            cp_async16(&Bs[buf][kr * BPAD + nc],
                       &B[(size_t)(k0 + kr) * N + n0 + nc]);
        }
    };

    load_tiles(0, 0);
    CP_COMMIT();

    const int nIter = K / 16;
    for (int it = 0; it < nIter; ++it) {
        CP_WAIT0();
        __syncthreads();
        if (it + 1 < nIter) {
            load_tiles((it + 1) & 1, (it + 1) * 16);
            CP_COMMIT();
        }
        const int buf = it & 1;
        const float* __restrict__ as = As[buf];
        const float* __restrict__ bs = Bs[buf];

#pragma unroll
        for (int ks = 0; ks < 2; ks++) {
            uint32_t af[4][4];
            uint32_t bf[4][2];
            const int cb = ks * 8 + tig;
#pragma unroll
            for (int mt = 0; mt < 4; mt++) {
                int r = wm + mt * 16 + group;
                af[mt][0] = __float_as_uint(as[r * APAD + cb]);
                af[mt][1] = __float_as_uint(as[(r + 8) * APAD + cb]);
                af[mt][2] = __float_as_uint(as[r * APAD + cb + 4]);
                af[mt][3] = __float_as_uint(as[(r + 8) * APAD + cb + 4]);
            }
            const int kr = ks * 8 + tig;
#pragma unroll
            for (int nt = 0; nt < 4; nt++) {
                int col = wn + nt * 8 + group;
                bf[nt][0] = __float_as_uint(bs[kr * BPAD + col]);
                bf[nt][1] = __float_as_uint(bs[(kr + 4) * BPAD + col]);
            }
#pragma unroll
            for (int mt = 0; mt < 4; mt++)
#pragma unroll
                for (int nt = 0; nt < 4; nt++) mma_tf32(acc[mt][nt], af[mt], bf[nt]);
        }
        __syncthreads();
    }

#pragma unroll
    for (int mt = 0; mt < 4; mt++) {
        int r = m0 + wm + mt * 16 + group;
#pragma unroll
        for (int nt = 0; nt < 4; nt++) {
            int cc = n0 + wn + nt * 8 + tig * 2;
            float4 v = acc[mt][nt];
            if (RND) {
                v.x = rnd_tf32(v.x); v.y = rnd_tf32(v.y);
                v.z = rnd_tf32(v.z); v.w = rnd_tf32(v.w);
            }
            *(float2*)&C[(size_t)r * N + cc]       = make_float2(v.x, v.y);
            *(float2*)&C[(size_t)(r + 8) * N + cc] = make_float2(v.z, v.w);
        }
    }
}

// ---------------------------------------------------------------------------
// RoPE in-place on q (heads 0..31) and k (heads 32..39); outputs tf32-rounded.
// ---------------------------------------------------------------------------
__global__ __launch_bounds__(256) void rope_kernel(float* __restrict__ qkv,
                                                   const int* __restrict__ positions) {
    const int token = blockIdx.x;
    const float pos = (float)positions[token];
    float* base_tok = qkv + (size_t)token * QKVW;
#pragma unroll
    for (int it = 0; it < 10; ++it) {
        int idx = it * 256 + threadIdx.x;
        int head = idx >> 6;
        int i = idx & 63;
        float inv_freq = 1.0f / powf(10000.0f, (float)i * (1.0f / 64.0f));
        float ang = pos * inv_freq;
        float cs = cosf(ang);
        float sn = sinf(ang);
        float* p = base_tok + head * HD;
        float x1 = p[i];
        float x2 = p[i + 64];
        p[i]      = rnd_tf32(x1 * cs - x2 * sn);
        p[i + 64] = rnd_tf32(x2 * cs + x1 * sn);
    }
}

// ---------------------------------------------------------------------------
// Tensor-core flash attention (tf32 mma, fp32 accum), causal.
// Block = 256 thr = 8 warps. Tile: 128 queries x 64 KV. Each warp owns 16
// query rows. Q/K/V/P staged in dynamic smem with conflict-free strides.
// Fragment maps (m16n8k8): A: a0=(g,t) a1=(g+8,t) a2=(g,t+4) a3=(g+8,t+4);
// B(col): b0=(k=t,n=g) b1=(k=t+4,n=g); C: (g,2t),(g,2t+1),(g+8,2t),(g+8,2t+1).
// ---------------------------------------------------------------------------
#define AT_BM 128
#define AT_BN 64
#define QS_STR 132
#define KS_STR 132
#define VS_STR 136
#define PS_STR 68
#define KS_OFF (AT_BM * QS_STR)            // 16896
#define VS_OFF (KS_OFF + AT_BN * KS_STR)   // 25344
#define PS_OFF (VS_OFF + AT_BN * VS_STR)   // 34048
#define AT_SMEM_FLOATS (PS_OFF + AT_BM * PS_STR)   // 42752
#define AT_SMEM_BYTES  (AT_SMEM_FLOATS * 4)        // 171008

__global__ __launch_bounds__(256, 1) void attn_tc(const float* __restrict__ qkv,
                                                  float* __restrict__ outp) {
    extern __shared__ float smf[];
    float* Qs = smf;
    float* Ks = smf + KS_OFF;
    float* Vs = smf + VS_OFF;
    float* Ps = smf + PS_OFF;

    const int tid  = threadIdx.x;
    const int warp = tid >> 5, lane = tid & 31;
    const int g    = lane >> 2, tig = lane & 3;
    const int qt   = gridDim.x - 1 - blockIdx.x;   // big tiles first
    const int h    = blockIdx.y, b = blockIdx.z;
    const int q0   = qt * AT_BM;
    const int wm   = warp * 16;

    // Load Q tile (pre-rounded by rope): 128 x 128
    const float* qbase = qkv + ((size_t)(b * S_LEN + q0)) * QKVW + h * HD;
#pragma unroll
    for (int u = 0; u < 16; u++) {
        int idx = tid + u * 256;
        int row = idx >> 5, c4 = idx & 31;
        *(float4*)&Qs[row * QS_STR + c4 * 4] =
            *(const float4*)(qbase + (size_t)row * QKVW + c4 * 4);
    }

    float4 o[16];
#pragma unroll
    for (int i = 0; i < 16; i++) o[i] = make_float4(0.f, 0.f, 0.f, 0.f);
    float m_lo = -INFINITY, m_hi = -INFINITY, l_lo = 0.f, l_hi = 0.f;

    const int kvh = h >> 2;                       // NH/NKV = 4
    const float* kbase = qkv + (size_t)b * S_LEN * QKVW + QSZ + kvh * HD;
    const int ntiles = (q0 + AT_BM) / AT_BN;
    const int row_lo = q0 + wm + g;
    const int warp_last_ks = q0 + wm + 15;        // last useful kv index for warp
    const float scale = 0.08838834764831845f;     // 1/sqrt(128)

    for (int tile = 0; tile < ntiles; tile++) {
        const int ks0 = tile * AT_BN;
        __syncthreads();   // previous iter's K/V reads done before overwrite
#pragma unroll
        for (int u = 0; u < 8; u++) {
            int idx = tid + u * 256;
            int row = idx >> 5, c4 = idx & 31;
            const float* src = kbase + (size_t)(ks0 + row) * QKVW + c4 * 4;
            cp_async16(&Ks[row * KS_STR + c4 * 4], src);
            cp_async16(&Vs[row * VS_STR + c4 * 4], src + KVSZ);
        }
        CP_COMMIT();
        CP_WAIT0();
        __syncthreads();

        if (ks0 > warp_last_ks) continue;  // tile fully masked for this warp

        // ---- S = scale * Q K^T  (16 k-steps over HD) ----
        float4 s[8];
#pragma unroll
        for (int nt = 0; nt < 8; nt++) s[nt] = make_float4(0.f, 0.f, 0.f, 0.f);
#pragma unroll
        for (int k = 0; k < 16; k++) {
            const int kc = k * 8 + tig;
            uint32_t a[4];
            a[0] = __float_as_uint(Qs[(wm + g) * QS_STR + kc]);
            a[1] = __float_as_uint(Qs[(wm + g + 8) * QS_STR + kc]);
            a[2] = __float_as_uint(Qs[(wm + g) * QS_STR + kc + 4]);
            a[3] = __float_as_uint(Qs[(wm + g + 8) * QS_STR + kc + 4]);
#pragma unroll
            for (int nt = 0; nt < 8; nt++) {
                uint32_t bb[2];
                bb[0] = __float_as_uint(Ks[(nt * 8 + g) * KS_STR + kc]);
                bb[1] = __float_as_uint(Ks[(nt * 8 + g) * KS_STR + kc + 4]);
                mma_tf32(s[nt], a, bb);
            }
        }

        // ---- scale + causal mask + row max ----
        float tmax_lo = -1e30f, tmax_hi = -1e30f;
#pragma unroll
        for (int nt = 0; nt < 8; nt++) {
            int col = ks0 + nt * 8 + 2 * tig;
            float4& v = s[nt];
            v.x *= scale; v.y *= scale; v.z *= scale; v.w *= scale;
            if (col     > row_lo)     v.x = -1e30f;
            if (col + 1 > row_lo)     v.y = -1e30f;
            if (col     > row_lo + 8) v.z = -1e30f;
            if (col + 1 > row_lo + 8) v.w = -1e30f;
            tmax_lo = fmaxf(tmax_lo, fmaxf(v.x, v.y));
            tmax_hi = fmaxf(tmax_hi, fmaxf(v.z, v.w));
        }
        tmax_lo = fmaxf(tmax_lo, __shfl_xor_sync(0xffffffffu, tmax_lo, 1));
        tmax_lo = fmaxf(tmax_lo, __shfl_xor_sync(0xffffffffu, tmax_lo, 2));
        tmax_hi = fmaxf(tmax_hi, __shfl_xor_sync(0xffffffffu, tmax_hi, 1));
        tmax_hi = fmaxf(tmax_hi, __shfl_xor_sync(0xffffffffu, tmax_hi, 2));

        float mn_lo = fmaxf(m_lo, tmax_lo);
        float mn_hi = fmaxf(m_hi, tmax_hi);
        float corr_lo = __expf(m_lo - mn_lo);
        float corr_hi = __expf(m_hi - mn_hi);
        m_lo = mn_lo; m_hi = mn_hi;

        // ---- exp + P store (tf32 rounded) + partial row sums ----
        float ps_lo = 0.f, ps_hi = 0.f;
#pragma unroll
        for (int nt = 0; nt < 8; nt++) {
            float4 v = s[nt];
            float ex = __expf(v.x - m_lo), ey = __expf(v.y - m_lo);
            float ez = __expf(v.z - m_hi), ew = __expf(v.w - m_hi);
            ps_lo += ex + ey;
            ps_hi += ez + ew;
            *(float2*)&Ps[(wm + g) * PS_STR + nt * 8 + 2 * tig] =
                make_float2(rnd_tf32(ex), rnd_tf32(ey));
            *(float2*)&Ps[(wm + g + 8) * PS_STR + nt * 8 + 2 * tig] =
                make_float2(rnd_tf32(ez), rnd_tf32(ew));
        }
        l_lo = l_lo * corr_lo + ps_lo;
        l_hi = l_hi * corr_hi + ps_hi;
#pragma unroll
        for (int i = 0; i < 16; i++) {
            o[i].x *= corr_lo; o[i].y *= corr_lo;
            o[i].z *= corr_hi; o[i].w *= corr_hi;
        }
        __syncwarp();   // Ps rows wm..wm+15 written & read by this warp only

        // ---- O += P V  (8 k-steps over BN, 16 n-tiles over HD) ----
#pragma unroll
        for (int k = 0; k < 8; k++) {
            const int kc = k * 8 + tig;
            uint32_t a[4];
            a[0] = __float_as_uint(Ps[(wm + g) * PS_STR + kc]);
            a[1] = __float_as_uint(Ps[(wm + g + 8) * PS_STR + kc]);
            a[2] = __float_as_uint(Ps[(wm + g) * PS_STR + kc + 4]);
            a[3] = __float_as_uint(Ps[(wm + g + 8) * PS_STR + kc + 4]);
#pragma unroll
            for (int ot = 0; ot < 16; ot++) {
                uint32_t bb[2];
                bb[0] = __float_as_uint(Vs[kc * VS_STR + ot * 8 + g]);
                bb[1] = __float_as_uint(Vs[(kc + 4) * VS_STR + ot * 8 + g]);
                mma_tf32(o[ot], a, bb);
            }
        }
    }

    // ---- epilogue: finish row sums, normalize, write tf32-rounded ----
    l_lo += __shfl_xor_sync(0xffffffffu, l_lo, 1);
    l_lo += __shfl_xor_sync(0xffffffffu, l_lo, 2);
    l_hi += __shfl_xor_sync(0xffffffffu, l_hi, 1);
    l_hi += __shfl_xor_sync(0xffffffffu, l_hi, 2);
    const float inv_lo = 1.f / l_lo;
    const float inv_hi = 1.f / l_hi;

    float* op_lo = outp + ((size_t)(b * S_LEN + row_lo)) * QSZ + h * HD;
    float* op_hi = op_lo + (size_t)8 * QSZ;
#pragma unroll
    for (int ot = 0; ot < 16; ot++) {
        int cc = ot * 8 + 2 * tig;
        *(float2*)&op_lo[cc] = make_float2(rnd_tf32(o[ot].x * inv_lo),
                                           rnd_tf32(o[ot].y * inv_lo));
        *(float2*)&op_hi[cc] = make_float2(rnd_tf32(o[ot].z * inv_hi),
                                           rnd_tf32(o[ot].w * inv_hi));
    }
}

// ---------------------------------------------------------------------------
// Launch: pre-round -> QKV GEMM (tf32) -> RoPE -> TC flash attn -> out GEMM
// ---------------------------------------------------------------------------
extern "C" void kernel_launch(void* const* d_in, const int* in_sizes, int n_in,
                              void* d_out, int out_size) {
    const int*   positions = (const int*)d_in[0];
    const float* hidden    = (const float*)d_in[1];
    const float* w_qkv     = (const float*)d_in[2];
    const float* w_o       = (const float*)d_in[3];
    float* out = (float*)d_out;

    float *qkv, *attn, *hid_r, *wqkv_r, *wo_r;
    cudaGetSymbolAddress((void**)&qkv,    g_qkv);
    cudaGetSymbolAddress((void**)&attn,   g_attn);
    cudaGetSymbolAddress((void**)&hid_r,  g_hid);
    cudaGetSymbolAddress((void**)&wqkv_r, g_wqkv);
    cudaGetSymbolAddress((void**)&wo_r,   g_wo);

    cudaFuncSetAttribute(attn_tc, cudaFuncAttributeMaxDynamicSharedMemorySize,
                         AT_SMEM_BYTES);

    // 0) Pre-round operands to tf32 (hoists all cvt out of GEMM inner loops)
    {
        int n4 = (NTOK * HID) / 4;
        round_tf32_kernel<<<(n4 + 255) / 256, 256>>>((const float4*)hidden, (float4*)hid_r, n4);
        n4 = (HID * QKVW) / 4;
        round_tf32_kernel<<<(n4 + 255) / 256, 256>>>((const float4*)w_qkv, (float4*)wqkv_r, n4);
        n4 = (QSZ * HID) / 4;
        round_tf32_kernel<<<(n4 + 255) / 256, 256>>>((const float4*)w_o, (float4*)wo_r, n4);
    }
    // 1) QKV projection (rounded epilogue: V feeds attention mma directly)
    gemm_tf32<true><<<dim3(QKVW / 128, NTOK / 128), 256>>>(hid_r, wqkv_r, qkv, NTOK, QKVW, HID);
    // 2) RoPE on q,k (tf32-rounded outputs)
    rope_kernel<<<NTOK, 256>>>(qkv, positions);
    // 3) Tensor-core causal flash attention
    attn_tc<<<dim3(S_LEN / AT_BM, NH, B_SZ), 256, AT_SMEM_BYTES>>>(qkv, attn);
    // 4) Output projection (full fp32 store)
    gemm_tf32<false><<<dim3(HID / 128, NTOK / 128), 256>>>(attn, wo_r, out, NTOK, HID, QSZ);
}

// round 7
// speedup vs baseline: 1.0031x; 1.0019x over previous
#include <cuda_runtime.h>
#include <math.h>
#include <stdint.h>

#define S_LEN 2048
#define B_SZ  2
#define NH    32
#define NKV   8
#define HD    128
#define HID   4096
#define QSZ   (NH*HD)        // 4096
#define KVSZ  (NKV*HD)       // 1024
#define QKVW  (QSZ + 2*KVSZ) // 6144
#define NTOK  (B_SZ*S_LEN)   // 4096

// Scratch (device globals: allocation-free per harness rules)
__device__ float g_qkv [(size_t)NTOK * QKVW];   // 100 MB
__device__ float g_attn[(size_t)NTOK * QSZ];    // 67 MB
__device__ float g_hid [(size_t)NTOK * HID];    // 67 MB  (tf32-rounded hidden)
__device__ float g_wqkv[(size_t)HID * QKVW];    // 100 MB (tf32-rounded w_qkv)
__device__ float g_wo  [(size_t)QSZ * HID];     // 67 MB  (tf32-rounded w_o)

// ---------------------------------------------------------------------------
// tf32 helpers
// ---------------------------------------------------------------------------
__device__ __forceinline__ uint32_t f2tf32(float x) {
    uint32_t r;
    asm("cvt.rna.tf32.f32 %0, %1;" : "=r"(r) : "f"(x));
    return r;
}
__device__ __forceinline__ float rnd_tf32(float x) {
    return __uint_as_float(f2tf32(x));
}

__device__ __forceinline__ void mma_tf32(float4& c, const uint32_t a[4], const uint32_t b[2]) {
    asm volatile(
        "mma.sync.aligned.m16n8k8.row.col.f32.tf32.tf32.f32 "
        "{%0,%1,%2,%3}, {%4,%5,%6,%7}, {%8,%9}, {%0,%1,%2,%3};\n"
        : "+f"(c.x), "+f"(c.y), "+f"(c.z), "+f"(c.w)
        : "r"(a[0]), "r"(a[1]), "r"(a[2]), "r"(a[3]),
          "r"(b[0]), "r"(b[1]));
}

__device__ __forceinline__ void cp_async16(void* smem, const void* gmem) {
    uint32_t s = (uint32_t)__cvta_generic_to_shared(smem);
    asm volatile("cp.async.cg.shared.global [%0], [%1], 16;\n" :: "r"(s), "l"(gmem));
}
#define CP_COMMIT() asm volatile("cp.async.commit_group;\n" ::: "memory")
#define CP_WAIT0()  asm volatile("cp.async.wait_group 0;\n" ::: "memory")

// ---------------------------------------------------------------------------
// Elementwise tf32 pre-rounding: out[i] = tf32(in[i]) (rna). n % 4 == 0.
// ---------------------------------------------------------------------------
__global__ __launch_bounds__(256) void round_tf32_kernel(const float4* __restrict__ in,
                                                         float4* __restrict__ out, int n4) {
    int i = blockIdx.x * blockDim.x + threadIdx.x;
    if (i < n4) {
        float4 v = in[i];
        v.x = rnd_tf32(v.x); v.y = rnd_tf32(v.y);
        v.z = rnd_tf32(v.z); v.w = rnd_tf32(v.w);
        out[i] = v;
    }
}

// ---------------------------------------------------------------------------
// TF32 tensor-core GEMM: C[M,N] = A[M,K]*B[K,N], row-major. Operands MUST be
// pre-rounded to tf32 (no cvt in the inner loop). 128x128 tile, BK=16,
// 8 warps (64x32 warp tile), cp.async double-buffered.
// RND: round C to tf32 on store (for tensors feeding later mma stages).
// ---------------------------------------------------------------------------
#define APAD 20
#define BPAD 132

template<bool RND>
__global__ __launch_bounds__(256, 2) void gemm_tf32(const float* __restrict__ A,
                                                    const float* __restrict__ B,
                                                    float* __restrict__ C,
                                                    int M, int N, int K) {
    __shared__ float As[2][128 * APAD];
    __shared__ float Bs[2][16 * BPAD];

    const int tid   = threadIdx.x;
    const int wid   = tid >> 5;
    const int lane  = tid & 31;
    const int group = lane >> 2;
    const int tig   = lane & 3;

    const int m0 = blockIdx.y * 128;
    const int n0 = blockIdx.x * 128;
    const int wm = (wid & 1) * 64;
    const int wn = (wid >> 1) * 32;

    float4 acc[4][4];
#pragma unroll
    for (int mt = 0; mt < 4; mt++)
#pragma unroll
        for (int nt = 0; nt < 4; nt++) acc[mt][nt] = make_float4(0.f, 0.f, 0.f, 0.f);

    auto load_tiles = [&](int buf, int k0) {
#pragma unroll
        for (int u = 0; u < 2; u++) {
            int id = tid + u * 256;
            int r  = id >> 2;
            int kc = (id & 3) * 4;
            cp_async16(&As[buf][r * APAD + kc],
                       &A[(size_t)(m0 + r) * K + k0 + kc]);
        }
#pragma unroll
        for (int u = 0; u < 2; u++) {
            int id = tid + u * 256;
            int kr = id >> 5;
            int nc = (id & 31) * 4;
            cp_async16(&Bs[buf][kr * BPAD + nc],
                       &B[(size_t)(k0 + kr) * N + n0 + nc]);
        }
    };

    load_tiles(0, 0);
    CP_COMMIT();

    const int nIter = K / 16;
    for (int it = 0; it < nIter; ++it) {
        CP_WAIT0();
        __syncthreads();
        if (it + 1 < nIter) {
            load_tiles((it + 1) & 1, (it + 1) * 16);
            CP_COMMIT();
        }
        const int buf = it & 1;
        const float* __restrict__ as = As[buf];
        const float* __restrict__ bs = Bs[buf];

#pragma unroll
        for (int ks = 0; ks < 2; ks++) {
            uint32_t af[4][4];
            uint32_t bf[4][2];
            const int cb = ks * 8 + tig;
#pragma unroll
            for (int mt = 0; mt < 4; mt++) {
                int r = wm + mt * 16 + group;
                af[mt][0] = __float_as_uint(as[r * APAD + cb]);
                af[mt][1] = __float_as_uint(as[(r + 8) * APAD + cb]);
                af[mt][2] = __float_as_uint(as[r * APAD + cb + 4]);
                af[mt][3] = __float_as_uint(as[(r + 8) * APAD + cb + 4]);
            }
            const int kr = ks * 8 + tig;
#pragma unroll
            for (int nt = 0; nt < 4; nt++) {
                int col = wn + nt * 8 + group;
                bf[nt][0] = __float_as_uint(bs[kr * BPAD + col]);
                bf[nt][1] = __float_as_uint(bs[(kr + 4) * BPAD + col]);
            }
#pragma unroll
            for (int mt = 0; mt < 4; mt++)
#pragma unroll
                for (int nt = 0; nt < 4; nt++) mma_tf32(acc[mt][nt], af[mt], bf[nt]);
        }
        __syncthreads();
    }

#pragma unroll
    for (int mt = 0; mt < 4; mt++) {
        int r = m0 + wm + mt * 16 + group;
#pragma unroll
        for (int nt = 0; nt < 4; nt++) {
            int cc = n0 + wn + nt * 8 + tig * 2;
            float4 v = acc[mt][nt];
            if (RND) {
                v.x = rnd_tf32(v.x); v.y = rnd_tf32(v.y);
                v.z = rnd_tf32(v.z); v.w = rnd_tf32(v.w);
            }
            *(float2*)&C[(size_t)r * N + cc]       = make_float2(v.x, v.y);
            *(float2*)&C[(size_t)(r + 8) * N + cc] = make_float2(v.z, v.w);
        }
    }
}

// ---------------------------------------------------------------------------
// RoPE in-place on q (heads 0..31) and k (heads 32..39); outputs tf32-rounded.
// ---------------------------------------------------------------------------
__global__ __launch_bounds__(256) void rope_kernel(float* __restrict__ qkv,
                                                   const int* __restrict__ positions) {
    const int token = blockIdx.x;
    const float pos = (float)positions[token];
    float* base_tok = qkv + (size_t)token * QKVW;
#pragma unroll
    for (int it = 0; it < 10; ++it) {
        int idx = it * 256 + threadIdx.x;
        int head = idx >> 6;
        int i = idx & 63;
        float inv_freq = 1.0f / powf(10000.0f, (float)i * (1.0f / 64.0f));
        float ang = pos * inv_freq;
        float cs = cosf(ang);
        float sn = sinf(ang);
        float* p = base_tok + head * HD;
        float x1 = p[i];
        float x2 = p[i + 64];
        p[i]      = rnd_tf32(x1 * cs - x2 * sn);
        p[i + 64] = rnd_tf32(x2 * cs + x1 * sn);
    }
}

// ---------------------------------------------------------------------------
// Tensor-core flash attention (tf32 mma, fp32 accum), causal.
// Block = 256 thr = 8 warps. Tile: 128 queries x 64 KV. Each warp owns 16
// query rows. Q/K/V/P staged in dynamic smem with conflict-free strides.
// Fragment maps (m16n8k8): A: a0=(g,t) a1=(g+8,t) a2=(g,t+4) a3=(g+8,t+4);
// B(col): b0=(k=t,n=g) b1=(k=t+4,n=g); C: (g,2t),(g,2t+1),(g+8,2t),(g+8,2t+1).
// ---------------------------------------------------------------------------
#define AT_BM 128
#define AT_BN 64
#define QS_STR 132
#define KS_STR 132
#define VS_STR 136
#define PS_STR 68
#define KS_OFF (AT_BM * QS_STR)            // 16896
#define VS_OFF (KS_OFF + AT_BN * KS_STR)   // 25344
#define PS_OFF (VS_OFF + AT_BN * VS_STR)   // 34048
#define AT_SMEM_FLOATS (PS_OFF + AT_BM * PS_STR)   // 42752
#define AT_SMEM_BYTES  (AT_SMEM_FLOATS * 4)        // 171008

__global__ __launch_bounds__(256, 1) void attn_tc(const float* __restrict__ qkv,
                                                  float* __restrict__ outp) {
    extern __shared__ float smf[];
    float* Qs = smf;
    float* Ks = smf + KS_OFF;
    float* Vs = smf + VS_OFF;
    float* Ps = smf + PS_OFF;

    const int tid  = threadIdx.x;
    const int warp = tid >> 5, lane = tid & 31;
    const int g    = lane >> 2, tig = lane & 3;
    const int qt   = gridDim.x - 1 - blockIdx.x;   // big tiles first
    const int h    = blockIdx.y, b = blockIdx.z;
    const int q0   = qt * AT_BM;
    const int wm   = warp * 16;

    // Load Q tile (pre-rounded by rope): 128 x 128
    const float* qbase = qkv + ((size_t)(b * S_LEN + q0)) * QKVW + h * HD;
#pragma unroll
    for (int u = 0; u < 16; u++) {
        int idx = tid + u * 256;
        int row = idx >> 5, c4 = idx & 31;
        *(float4*)&Qs[row * QS_STR + c4 * 4] =
            *(const float4*)(qbase + (size_t)row * QKVW + c4 * 4);
    }

    float4 o[16];
#pragma unroll
    for (int i = 0; i < 16; i++) o[i] = make_float4(0.f, 0.f, 0.f, 0.f);
    float m_lo = -INFINITY, m_hi = -INFINITY, l_lo = 0.f, l_hi = 0.f;

    const int kvh = h >> 2;                       // NH/NKV = 4
    const float* kbase = qkv + (size_t)b * S_LEN * QKVW + QSZ + kvh * HD;
    const int ntiles = (q0 + AT_BM) / AT_BN;
    const int row_lo = q0 + wm + g;
    const int warp_last_ks = q0 + wm + 15;        // last useful kv index for warp
    const float scale = 0.08838834764831845f;     // 1/sqrt(128)

    for (int tile = 0; tile < ntiles; tile++) {
        const int ks0 = tile * AT_BN;
        __syncthreads();   // previous iter's K/V reads done before overwrite
#pragma unroll
        for (int u = 0; u < 8; u++) {
            int idx = tid + u * 256;
            int row = idx >> 5, c4 = idx & 31;
            const float* src = kbase + (size_t)(ks0 + row) * QKVW + c4 * 4;
            cp_async16(&Ks[row * KS_STR + c4 * 4], src);
            cp_async16(&Vs[row * VS_STR + c4 * 4], src + KVSZ);
        }
        CP_COMMIT();
        CP_WAIT0();
        __syncthreads();

        if (ks0 > warp_last_ks) continue;  // tile fully masked for this warp

        // ---- S = scale * Q K^T  (16 k-steps over HD) ----
        float4 s[8];
#pragma unroll
        for (int nt = 0; nt < 8; nt++) s[nt] = make_float4(0.f, 0.f, 0.f, 0.f);
#pragma unroll
        for (int k = 0; k < 16; k++) {
            const int kc = k * 8 + tig;
            uint32_t a[4];
            a[0] = __float_as_uint(Qs[(wm + g) * QS_STR + kc]);
            a[1] = __float_as_uint(Qs[(wm + g + 8) * QS_STR + kc]);
            a[2] = __float_as_uint(Qs[(wm + g) * QS_STR + kc + 4]);
            a[3] = __float_as_uint(Qs[(wm + g + 8) * QS_STR + kc + 4]);
#pragma unroll
            for (int nt = 0; nt < 8; nt++) {
                uint32_t bb[2];
                bb[0] = __float_as_uint(Ks[(nt * 8 + g) * KS_STR + kc]);
                bb[1] = __float_as_uint(Ks[(nt * 8 + g) * KS_STR + kc + 4]);
                mma_tf32(s[nt], a, bb);
            }
        }

        // ---- scale + causal mask + row max ----
        float tmax_lo = -1e30f, tmax_hi = -1e30f;
#pragma unroll
        for (int nt = 0; nt < 8; nt++) {
            int col = ks0 + nt * 8 + 2 * tig;
            float4& v = s[nt];
            v.x *= scale; v.y *= scale; v.z *= scale; v.w *= scale;
            if (col     > row_lo)     v.x = -1e30f;
            if (col + 1 > row_lo)     v.y = -1e30f;
            if (col     > row_lo + 8) v.z = -1e30f;
            if (col + 1 > row_lo + 8) v.w = -1e30f;
            tmax_lo = fmaxf(tmax_lo, fmaxf(v.x, v.y));
            tmax_hi = fmaxf(tmax_hi, fmaxf(v.z, v.w));
        }
        tmax_lo = fmaxf(tmax_lo, __shfl_xor_sync(0xffffffffu, tmax_lo, 1));
        tmax_lo = fmaxf(tmax_lo, __shfl_xor_sync(0xffffffffu, tmax_lo, 2));
        tmax_hi = fmaxf(tmax_hi, __shfl_xor_sync(0xffffffffu, tmax_hi, 1));
        tmax_hi = fmaxf(tmax_hi, __shfl_xor_sync(0xffffffffu, tmax_hi, 2));

        float mn_lo = fmaxf(m_lo, tmax_lo);
        float mn_hi = fmaxf(m_hi, tmax_hi);
        float corr_lo = __expf(m_lo - mn_lo);
        float corr_hi = __expf(m_hi - mn_hi);
        m_lo = mn_lo; m_hi = mn_hi;

        // ---- exp + P store (tf32 rounded) + partial row sums ----
        float ps_lo = 0.f, ps_hi = 0.f;
#pragma unroll
        for (int nt = 0; nt < 8; nt++) {
            float4 v = s[nt];
            float ex = __expf(v.x - m_lo), ey = __expf(v.y - m_lo);
            float ez = __expf(v.z - m_hi), ew = __expf(v.w - m_hi);
            ps_lo += ex + ey;
            ps_hi += ez + ew;
            *(float2*)&Ps[(wm + g) * PS_STR + nt * 8 + 2 * tig] =
                make_float2(rnd_tf32(ex), rnd_tf32(ey));
            *(float2*)&Ps[(wm + g + 8) * PS_STR + nt * 8 + 2 * tig] =
                make_float2(rnd_tf32(ez), rnd_tf32(ew));
        }
        l_lo = l_lo * corr_lo + ps_lo;
        l_hi = l_hi * corr_hi + ps_hi;
#pragma unroll
        for (int i = 0; i < 16; i++) {
            o[i].x *= corr_lo; o[i].y *= corr_lo;
            o[i].z *= corr_hi; o[i].w *= corr_hi;
        }
        __syncwarp();   // Ps rows wm..wm+15 written & read by this warp only

        // ---- O += P V  (8 k-steps over BN, 16 n-tiles over HD) ----
#pragma unroll
        for (int k = 0; k < 8; k++) {
            const int kc = k * 8 + tig;
            uint32_t a[4];
            a[0] = __float_as_uint(Ps[(wm + g) * PS_STR + kc]);
            a[1] = __float_as_uint(Ps[(wm + g + 8) * PS_STR + kc]);
            a[2] = __float_as_uint(Ps[(wm + g) * PS_STR + kc + 4]);
            a[3] = __float_as_uint(Ps[(wm + g + 8) * PS_STR + kc + 4]);
#pragma unroll
            for (int ot = 0; ot < 16; ot++) {
                uint32_t bb[2];
                bb[0] = __float_as_uint(Vs[kc * VS_STR + ot * 8 + g]);
                bb[1] = __float_as_uint(Vs[(kc + 4) * VS_STR + ot * 8 + g]);
                mma_tf32(o[ot], a, bb);
            }
        }
    }

    // ---- epilogue: finish row sums, normalize, write tf32-rounded ----
    l_lo += __shfl_xor_sync(0xffffffffu, l_lo, 1);
    l_lo += __shfl_xor_sync(0xffffffffu, l_lo, 2);
    l_hi += __shfl_xor_sync(0xffffffffu, l_hi, 1);
    l_hi += __shfl_xor_sync(0xffffffffu, l_hi, 2);
    const float inv_lo = 1.f / l_lo;
    const float inv_hi = 1.f / l_hi;

    float* op_lo = outp + ((size_t)(b * S_LEN + row_lo)) * QSZ + h * HD;
    float* op_hi = op_lo + (size_t)8 * QSZ;
#pragma unroll
    for (int ot = 0; ot < 16; ot++) {
        int cc = ot * 8 + 2 * tig;
        *(float2*)&op_lo[cc] = make_float2(rnd_tf32(o[ot].x * inv_lo),
                                           rnd_tf32(o[ot].y * inv_lo));
        *(float2*)&op_hi[cc] = make_float2(rnd_tf32(o[ot].z * inv_hi),
                                           rnd_tf32(o[ot].w * inv_hi));
    }
}

// ---------------------------------------------------------------------------
// Launch: pre-round -> QKV GEMM (tf32) -> RoPE -> TC flash attn -> out GEMM
// ---------------------------------------------------------------------------
extern "C" void kernel_launch(void* const* d_in, const int* in_sizes, int n_in,
                              void* d_out, int out_size) {
    const int*   positions = (const int*)d_in[0];
    const float* hidden    = (const float*)d_in[1];
    const float* w_qkv     = (const float*)d_in[2];
    const float* w_o       = (const float*)d_in[3];
    float* out = (float*)d_out;

    float *qkv, *attn, *hid_r, *wqkv_r, *wo_r;
    cudaGetSymbolAddress((void**)&qkv,    g_qkv);
    cudaGetSymbolAddress((void**)&attn,   g_attn);
    cudaGetSymbolAddress((void**)&hid_r,  g_hid);
    cudaGetSymbolAddress((void**)&wqkv_r, g_wqkv);
    cudaGetSymbolAddress((void**)&wo_r,   g_wo);

    cudaFuncSetAttribute(attn_tc, cudaFuncAttributeMaxDynamicSharedMemorySize,
                         AT_SMEM_BYTES);

    // 0) Pre-round operands to tf32 (hoists all cvt out of GEMM inner loops)
    {
        int n4 = (NTOK * HID) / 4;
        round_tf32_kernel<<<(n4 + 255) / 256, 256>>>((const float4*)hidden, (float4*)hid_r, n4);
        n4 = (HID * QKVW) / 4;
        round_tf32_kernel<<<(n4 + 255) / 256, 256>>>((const float4*)w_qkv, (float4*)wqkv_r, n4);
        n4 = (QSZ * HID) / 4;
        round_tf32_kernel<<<(n4 + 255) / 256, 256>>>((const float4*)w_o, (float4*)wo_r, n4);
    }
    // 1) QKV projection (rounded epilogue: V feeds attention mma directly)
    gemm_tf32<true><<<dim3(QKVW / 128, NTOK / 128), 256>>>(hid_r, wqkv_r, qkv, NTOK, QKVW, HID);
    // 2) RoPE on q,k (tf32-rounded outputs)
    rope_kernel<<<NTOK, 256>>>(qkv, positions);
    // 3) Tensor-core causal flash attention
    attn_tc<<<dim3(S_LEN / AT_BM, NH, B_SZ), 256, AT_SMEM_BYTES>>>(qkv, attn);
    // 4) Output projection (full fp32 store)
    gemm_tf32<false><<<dim3(HID / 128, NTOK / 128), 256>>>(attn, wo_r, out, NTOK, HID, QSZ);
}